// round 4
// baseline (speedup 1.0000x reference)
#include <cuda_runtime.h>
#include <math.h>

// ---------------------------------------------------------------------------
// Round 4: L1-replay + MOV elimination.
//  - t / v feature phases staged through smem (coalesced float4), invariants
//    computed from LDS (kills ~9x LDG line-replays).
//  - GEMM1: dup-stored A (featdup) -> LDS.128 yields f32x2 operands directly,
//    zero MOVs; W1 pair-transposed, broadcast LDS.128 covers 2 k per load.
// ---------------------------------------------------------------------------

#define MTILE 64
#define NTHREADS 256

// smem float offsets
#define FD_PITCH   136                // dup row: 128 floats + 8 pad (16B mult)
#define OFF_FD     0                  // featdup [32][136] = 4352
#define OFF_W1P    4352               // w1p [80 pairs][68] = 5440  (end 9792)
#define OFF_STAGE  9792               // t/v slab stage: 9216 floats (36KB)
#define SMEM_FLOATS 19008             // 76032 B high-water
#define OFF_HT     0                  // hT [160][68] = 10880 (phase 2)
#define OFF_ALPHA  0                  // alpha [64][65] (phase 3)
#define OFF_GS     4352               // Gs [64][9] (phase 4)
#define SMEM_BYTES (SMEM_FLOATS * 4)

typedef unsigned long long ull;

__device__ __forceinline__ void fma2(ull& d, ull a, ull b) {
    asm("fma.rn.f32x2 %0, %1, %2, %0;" : "+l"(d) : "l"(a), "l"(b));
}
__device__ __forceinline__ void upk2(float& x, float& y, ull v) {
    asm("mov.b64 {%0, %1}, %2;" : "=f"(x), "=f"(y) : "l"(v));
}
__device__ __forceinline__ ull pk2(float x, float y) {
    ull r; asm("mov.b64 %0, {%1, %2};" : "=l"(r) : "f"(x), "f"(y)); return r;
}

__global__ void __launch_bounds__(NTHREADS, 3)
tensor_message_fused(const float* __restrict__ h,
                     const float* __restrict__ v,
                     const float* __restrict__ t,
                     const float* __restrict__ frames,
                     const int* __restrict__ batch,
                     const float* __restrict__ W1,
                     const float* __restrict__ b1,
                     const float* __restrict__ W2,
                     const float* __restrict__ b2,
                     float* __restrict__ out,
                     int N, int num_graphs)
{
    extern __shared__ float s[];
    const int tid  = threadIdx.x;
    const int lane = tid & 31;
    const int wid  = tid >> 5;            // 0..7
    const int m0   = blockIdx.x * MTILE;
    const int mlim = (N - m0 < MTILE) ? (N - m0) : MTILE;

    // GEMM1 mapping: warp wid -> cols [20*wid, 20*wid+20); lane -> rows 2*lane, 2*lane+1
    const int p0 = wid * 10;              // first W1 pair index for this warp

    ull acc[2][10];
#pragma unroll
    for (int r = 0; r < 2; ++r)
#pragma unroll
        for (int j = 0; j < 10; ++j) acc[r][j] = 0ULL;

    for (int kc = 0; kc < 320; kc += 32) {
        // ---------------- build featdup chunk [32 k][64 nodes dup] ----------
        if (kc < 128) {
            // h channels: coalesced gmem read, dup STS.64 write
            for (int i = tid; i < MTILE * 32; i += NTHREADS) {
                int m = i >> 5, k = i & 31;
                float val = 0.0f;
                if (m < mlim) val = h[(size_t)(m0 + m) * 128 + kc + k];
                *reinterpret_cast<float2*>(&s[OFF_FD + k * FD_PITCH + 2 * m]) =
                    make_float2(val, val);
            }
            // stage W1 pair-transposed: w1p[n>>1][2k + (n&1)]
            for (int i = tid; i < 32 * 160; i += NTHREADS) {
                int k = i / 160, n = i - k * 160;
                s[OFF_W1P + (n >> 1) * 68 + 2 * k + (n & 1)] =
                    W1[(size_t)(kc + k) * 160 + n];
            }
            __syncthreads();
        } else if (kc < 192) {
            // ---- v slab -> smem (coalesced), then norms from LDS ----
            const int j0 = kc - 128;
            for (int i = tid; i < MTILE * 24; i += NTHREADS) {   // 1536 float4
                int node = i / 24, q = i - node * 24;
                float4 val = make_float4(0.f, 0.f, 0.f, 0.f);
                if (node < mlim)
                    val = reinterpret_cast<const float4*>(
                        v + ((size_t)(m0 + node) * 64 + j0) * 3)[q];
                reinterpret_cast<float4*>(&s[OFF_STAGE])[i] = val;
            }
            for (int i = tid; i < 32 * 160; i += NTHREADS) {
                int k = i / 160, n = i - k * 160;
                s[OFF_W1P + (n >> 1) * 68 + 2 * k + (n & 1)] =
                    W1[(size_t)(kc + k) * 160 + n];
            }
            __syncthreads();
            for (int i = tid; i < MTILE * 32; i += NTHREADS) {
                int m = i >> 5, k = i & 31;
                const float* sp = &s[OFF_STAGE + m * 96 + k * 3];
                float x = sp[0], y = sp[1], z = sp[2];
                float val = sqrtf(x * x + y * y + z * z);
                *reinterpret_cast<float2*>(&s[OFF_FD + k * FD_PITCH + 2 * m]) =
                    make_float2(val, val);
            }
            __syncthreads();
        } else {
            // ---- t slab (16 channels) -> smem, invariants from LDS ----
            const int c0 = (kc - 192) >> 1;
            for (int i = tid; i < MTILE * 36; i += NTHREADS) {   // 2304 float4
                int node = i / 36, q = i - node * 36;
                float4 val = make_float4(0.f, 0.f, 0.f, 0.f);
                if (node < mlim)
                    val = reinterpret_cast<const float4*>(
                        t + ((size_t)(m0 + node) * 64 + c0) * 9)[q];
                reinterpret_cast<float4*>(&s[OFF_STAGE])[i] = val;
            }
            for (int i = tid; i < 32 * 160; i += NTHREADS) {
                int k = i / 160, n = i - k * 160;
                s[OFF_W1P + (n >> 1) * 68 + 2 * k + (n & 1)] =
                    W1[(size_t)(kc + k) * 160 + n];
            }
            __syncthreads();
            for (int i = tid; i < MTILE * 16; i += NTHREADS) {
                int m = i >> 4, cc = i & 15;
                const float* sp = &s[OFF_STAGE + m * 144 + cc * 9];
                float q0 = sp[0], q1 = sp[1], q2 = sp[2];
                float q3 = sp[3], q4 = sp[4], q5 = sp[5];
                float q6 = sp[6], q7 = sp[7], q8 = sp[8];
                float tr = q0 + q4 + q8;
                float fb = sqrtf(q0*q0 + q1*q1 + q2*q2 + q3*q3 + q4*q4 +
                                 q5*q5 + q6*q6 + q7*q7 + q8*q8);
                *reinterpret_cast<float2*>(
                    &s[OFF_FD + (2 * cc) * FD_PITCH + 2 * m]) = make_float2(tr, tr);
                *reinterpret_cast<float2*>(
                    &s[OFF_FD + (2 * cc + 1) * FD_PITCH + 2 * m]) = make_float2(fb, fb);
            }
            __syncthreads();
        }

        // ---------------- GEMM1 inner: 2 k per iteration --------------------
#pragma unroll 4
        for (int k = 0; k < 32; k += 2) {
            const ulonglong2 a0 = *reinterpret_cast<const ulonglong2*>(
                &s[OFF_FD + k * FD_PITCH + 4 * lane]);          // {f2l,f2l},{f2l+1,f2l+1}
            const ulonglong2 a1 = *reinterpret_cast<const ulonglong2*>(
                &s[OFF_FD + (k + 1) * FD_PITCH + 4 * lane]);
#pragma unroll
            for (int j = 0; j < 10; ++j) {
                const ulonglong2 b = *reinterpret_cast<const ulonglong2*>(
                    &s[OFF_W1P + (p0 + j) * 68 + 2 * k]);       // pair@k, pair@k+1
                fma2(acc[0][j], a0.x, b.x);
                fma2(acc[1][j], a0.y, b.x);
                fma2(acc[0][j], a1.x, b.y);
                fma2(acc[1][j], a1.y, b.y);
            }
        }
        __syncthreads();
    }

    // ---------------- bias + SiLU -> hT [160][68] ---------------------------
#pragma unroll
    for (int j = 0; j < 10; ++j) {
        const int c0 = 2 * (p0 + j);
        const float bl = b1[c0], bh = b1[c0 + 1];
        float x0l, x0h, x1l, x1h;
        upk2(x0l, x0h, acc[0][j]);   // node 2l: cols c0, c0+1
        upk2(x1l, x1h, acc[1][j]);   // node 2l+1
        x0l += bl; x0h += bh; x1l += bl; x1h += bh;
        float s0l = x0l / (1.0f + __expf(-x0l));
        float s0h = x0h / (1.0f + __expf(-x0h));
        float s1l = x1l / (1.0f + __expf(-x1l));
        float s1h = x1h / (1.0f + __expf(-x1h));
        *reinterpret_cast<float2*>(&s[OFF_HT + c0 * 68 + 2 * lane]) =
            make_float2(s0l, s1l);
        *reinterpret_cast<float2*>(&s[OFF_HT + (c0 + 1) * 68 + 2 * lane]) =
            make_float2(s0h, s1h);
    }
    __syncthreads();

    // ---------------- GEMM2: [64,160] @ [160,64] ----------------------------
    const int tm  = (tid & 15) * 4;
    const int tn2 = (tid >> 4) * 4;
    ull acc2[4][2];
#pragma unroll
    for (int i = 0; i < 4; ++i) { acc2[i][0] = 0ULL; acc2[i][1] = 0ULL; }

#pragma unroll 4
    for (int k = 0; k < 160; ++k) {
        const float4 a4 = *reinterpret_cast<const float4*>(&s[OFF_HT + k * 68 + tm]);
        const ulonglong2 b2v = *reinterpret_cast<const ulonglong2*>(
            &W2[(size_t)k * 64 + tn2]);
        ull avd[4];
        avd[0] = pk2(a4.x, a4.x);
        avd[1] = pk2(a4.y, a4.y);
        avd[2] = pk2(a4.z, a4.z);
        avd[3] = pk2(a4.w, a4.w);
#pragma unroll
        for (int i = 0; i < 4; ++i) {
            fma2(acc2[i][0], avd[i], b2v.x);
            fma2(acc2[i][1], avd[i], b2v.y);
        }
    }
    __syncthreads();   // hT reads done; alpha overlays

    {
        const float b_0 = b2[tn2 + 0], b_1 = b2[tn2 + 1];
        const float b_2 = b2[tn2 + 2], b_3 = b2[tn2 + 3];
#pragma unroll
        for (int i = 0; i < 4; ++i) {
            float a0, a1, a2, a3;
            upk2(a0, a1, acc2[i][0]);
            upk2(a2, a3, acc2[i][1]);
            float* ap = &s[OFF_ALPHA + (tm + i) * 65 + tn2];
            ap[0] = a0 + b_0; ap[1] = a1 + b_1;
            ap[2] = a2 + b_2; ap[3] = a3 + b_3;
        }
    }
    __syncthreads();

    // ---------------- epilogue: gated sum, symmetrize, rotate ---------------
    const int node = tid >> 2;
    const int jj   = tid & 3;
    float g[9];
#pragma unroll
    for (int k = 0; k < 9; ++k) g[k] = 0.0f;

    if (node < mlim) {
        const float4* tp4 = reinterpret_cast<const float4*>(
            t + ((size_t)(m0 + node) * 64 + jj * 16) * 9);
        const float* ap = &s[OFF_ALPHA + node * 65 + jj * 16];
#pragma unroll
        for (int cb = 0; cb < 4; ++cb) {
            float4 q[9];
#pragma unroll
            for (int u = 0; u < 9; ++u) q[u] = tp4[cb * 9 + u];
            const float* f = reinterpret_cast<const float*>(q);
            float al[4];
#pragma unroll
            for (int c = 0; c < 4; ++c) al[c] = ap[cb * 4 + c];
#pragma unroll
            for (int c = 0; c < 4; ++c)
#pragma unroll
                for (int k = 0; k < 9; ++k)
                    g[k] = fmaf(al[c], f[c * 9 + k], g[k]);
        }
    }
#pragma unroll
    for (int k = 0; k < 9; ++k) {
        g[k] += __shfl_xor_sync(0xFFFFFFFFu, g[k], 1);
        g[k] += __shfl_xor_sync(0xFFFFFFFFu, g[k], 2);
    }

    if (jj == 0) {
        float G[9];
        if (node < mlim) {
            float S[9];
#pragma unroll
            for (int a = 0; a < 3; ++a)
#pragma unroll
                for (int b = 0; b < 3; ++b)
                    S[a * 3 + b] = 0.5f * (g[a * 3 + b] + g[b * 3 + a]);
            const float* rp = frames + (size_t)(m0 + node) * 9;
            float R[9];
#pragma unroll
            for (int k = 0; k < 9; ++k) R[k] = rp[k];
            float P[9];
#pragma unroll
            for (int a = 0; a < 3; ++a)
#pragma unroll
                for (int c = 0; c < 3; ++c)
                    P[a * 3 + c] = R[a * 3 + 0] * S[0 * 3 + c]
                                 + R[a * 3 + 1] * S[1 * 3 + c]
                                 + R[a * 3 + 2] * S[2 * 3 + c];
#pragma unroll
            for (int a = 0; a < 3; ++a)
#pragma unroll
                for (int d = 0; d < 3; ++d)
                    G[a * 3 + d] = P[a * 3 + 0] * R[d * 3 + 0]
                                 + P[a * 3 + 1] * R[d * 3 + 1]
                                 + P[a * 3 + 2] * R[d * 3 + 2];
        } else {
#pragma unroll
            for (int k = 0; k < 9; ++k) G[k] = 0.0f;
        }
#pragma unroll
        for (int k = 0; k < 9; ++k) s[OFF_GS + node * 9 + k] = G[k];
    }
    __syncthreads();

    // ---------------- sorted-run segment sum --------------------------------
    if (tid < 9) {
        int cur = batch[m0];
        float run = 0.0f;
        for (int n = 0; n < mlim; ++n) {
            int b = batch[m0 + n];
            if (b != cur) {
                if ((unsigned)cur < (unsigned)num_graphs)
                    atomicAdd(&out[(size_t)cur * 9 + tid], run);
                run = 0.0f;
                cur = b;
            }
            run += s[OFF_GS + n * 9 + tid];
        }
        if ((unsigned)cur < (unsigned)num_graphs)
            atomicAdd(&out[(size_t)cur * 9 + tid], run);
    }
}

extern "C" void kernel_launch(void* const* d_in, const int* in_sizes, int n_in,
                              void* d_out, int out_size)
{
    const float* h      = (const float*)d_in[0];
    const float* v      = (const float*)d_in[1];
    const float* t      = (const float*)d_in[2];
    const float* frames = (const float*)d_in[3];
    const int*   batch  = (const int*)d_in[4];
    const float* W1     = (const float*)d_in[5];
    const float* b1     = (const float*)d_in[6];
    const float* W2     = (const float*)d_in[7];
    const float* b2     = (const float*)d_in[8];
    float* out = (float*)d_out;

    const int N = in_sizes[0] / 128;
    const int num_graphs = out_size / 9;

    cudaMemsetAsync(d_out, 0, (size_t)out_size * sizeof(float));

    cudaFuncSetAttribute(tensor_message_fused,
                         cudaFuncAttributeMaxDynamicSharedMemorySize, SMEM_BYTES);

    const int grid = (N + MTILE - 1) / MTILE;
    tensor_message_fused<<<grid, NTHREADS, SMEM_BYTES>>>(
        h, v, t, frames, batch, W1, b1, W2, b2, out, N, num_graphs);
}

// round 5
// speedup vs baseline: 1.3164x; 1.3164x over previous
#include <cuda_runtime.h>
#include <math.h>

// ---------------------------------------------------------------------------
// Round 5: round-3 structure (it was the best) + occupancy via register cap.
// 80 regs * 256 thr = 20.5K regs/CTA capped occupancy at 3 CTAs/SM (regfile).
// __launch_bounds__(256,4) -> <=64 regs -> 4 CTAs/SM (smem 43.5KB*4 fits).
// Also: batch[] staged to smem for the tail scan (kills serial LDG chain).
// ---------------------------------------------------------------------------

#define MTILE 64
#define NTHREADS 256
#define FEAT_PITCH 68

// smem float offsets (regions overlaid across phases, separated by barriers)
#define OFF_FEAT   0        // feat chunk [32][68]   -> 2176 floats
#define OFF_W1S    2176     // W1 chunk  [32][160]  -> 5120 floats (end 7296)
#define OFF_HT     0        // hT [160][68]         -> 10880 floats (phase 2)
#define OFF_ALPHA  0        // alpha [64][65]       -> 4160 floats (phase 3)
#define OFF_GS     4352     // Gs [64][9]           -> 576 floats  (phase 4)
#define OFF_BATCH  4928     // batch[64] as ints    -> 64 slots
#define SMEM_FLOATS 10880
#define SMEM_BYTES  (SMEM_FLOATS * 4)

typedef unsigned long long ull;

__device__ __forceinline__ ull pk2(float x, float y) {
    ull r; asm("mov.b64 %0, {%1, %2};" : "=l"(r) : "f"(x), "f"(y)); return r;
}
__device__ __forceinline__ void upk2(float& x, float& y, ull v) {
    asm("mov.b64 {%0, %1}, %2;" : "=f"(x), "=f"(y) : "l"(v));
}
__device__ __forceinline__ void fma2(ull& d, ull a, ull b) {
    asm("fma.rn.f32x2 %0, %1, %2, %0;" : "+l"(d) : "l"(a), "l"(b));
}

__global__ void __launch_bounds__(NTHREADS, 4)
tensor_message_fused(const float* __restrict__ h,
                     const float* __restrict__ v,
                     const float* __restrict__ t,
                     const float* __restrict__ frames,
                     const int* __restrict__ batch,
                     const float* __restrict__ W1,
                     const float* __restrict__ b1,
                     const float* __restrict__ W2,
                     const float* __restrict__ b2,
                     float* __restrict__ out,
                     int N, int num_graphs)
{
    extern __shared__ float s[];
    const int tid = threadIdx.x;
    const int m0  = blockIdx.x * MTILE;
    const int mlim = (N - m0 < MTILE) ? (N - m0) : MTILE;

    // ======================= GEMM1: [64,320] @ [320,160] ====================
    const int tm  = (tid & 15) * 4;    // 4 node-rows
    const int tn  = (tid >> 4) * 10;   // 10 hidden cols (5 packed pairs)

    ull accp[4][5];
#pragma unroll
    for (int i = 0; i < 4; ++i)
#pragma unroll
        for (int j = 0; j < 5; ++j) accp[i][j] = 0ULL;

    for (int kc = 0; kc < 320; kc += 32) {
        // ---- build feature chunk [32 k-rows][64 nodes] ----
        if (kc < 128) {
            for (int i = tid; i < MTILE * 32; i += NTHREADS) {
                int m = i >> 5, k = i & 31;
                float val = 0.0f;
                if (m < mlim) val = h[(size_t)(m0 + m) * 128 + kc + k];
                s[OFF_FEAT + k * FEAT_PITCH + m] = val;
            }
        } else if (kc < 192) {
            const int j0 = kc - 128;
            for (int i = tid; i < MTILE * 32; i += NTHREADS) {
                int m = i >> 5, k = i & 31;
                float val = 0.0f;
                if (m < mlim) {
                    const float* vp = v + ((size_t)(m0 + m) * 64 + j0 + k) * 3;
                    float x = vp[0], y = vp[1], z = vp[2];
                    val = sqrtf(x * x + y * y + z * z);
                }
                s[OFF_FEAT + k * FEAT_PITCH + m] = val;
            }
        } else {
            const int c0 = (kc - 192) >> 1;
            for (int i = tid; i < MTILE * 16; i += NTHREADS) {
                int m = i >> 4, cc = i & 15;
                float tr = 0.0f, fb = 0.0f;
                if (m < mlim) {
                    const float* tp = t + ((size_t)(m0 + m) * 64 + c0 + cc) * 9;
                    float q0 = tp[0], q1 = tp[1], q2 = tp[2];
                    float q3 = tp[3], q4 = tp[4], q5 = tp[5];
                    float q6 = tp[6], q7 = tp[7], q8 = tp[8];
                    tr = q0 + q4 + q8;
                    fb = sqrtf(q0*q0 + q1*q1 + q2*q2 + q3*q3 + q4*q4 +
                               q5*q5 + q6*q6 + q7*q7 + q8*q8);
                }
                s[OFF_FEAT + (2 * cc)     * FEAT_PITCH + m] = tr;
                s[OFF_FEAT + (2 * cc + 1) * FEAT_PITCH + m] = fb;
            }
        }
        // ---- stage W1 chunk [32][160] (linear copy, trivial addressing) ----
        for (int i = tid; i < 32 * 160; i += NTHREADS)
            s[OFF_W1S + i] = W1[(size_t)kc * 160 + i];
        __syncthreads();

#pragma unroll 4
        for (int k = 0; k < 32; ++k) {
            const float4 a4 = *reinterpret_cast<const float4*>(
                &s[OFF_FEAT + k * FEAT_PITCH + tm]);
            ull avd[4];
            avd[0] = pk2(a4.x, a4.x);
            avd[1] = pk2(a4.y, a4.y);
            avd[2] = pk2(a4.z, a4.z);
            avd[3] = pk2(a4.w, a4.w);
            const ull* bp = reinterpret_cast<const ull*>(
                &s[OFF_W1S + k * 160 + tn]);
            ull bv2[5];
#pragma unroll
            for (int j = 0; j < 5; ++j) bv2[j] = bp[j];
#pragma unroll
            for (int i = 0; i < 4; ++i)
#pragma unroll
                for (int j = 0; j < 5; ++j)
                    fma2(accp[i][j], avd[i], bv2[j]);
        }
        __syncthreads();
    }

    // bias + SiLU, write hT (overlays feat/W1 regions — barrier above protects)
#pragma unroll
    for (int j2 = 0; j2 < 5; ++j2) {
        const float b_lo = b1[tn + 2 * j2];
        const float b_hi = b1[tn + 2 * j2 + 1];
#pragma unroll
        for (int i = 0; i < 4; ++i) {
            float lo, hi;
            upk2(lo, hi, accp[i][j2]);
            float x0 = lo + b_lo, x1 = hi + b_hi;
            float s0 = x0 / (1.0f + __expf(-x0));
            float s1 = x1 / (1.0f + __expf(-x1));
            s[OFF_HT + (tn + 2 * j2)     * FEAT_PITCH + tm + i] = s0;
            s[OFF_HT + (tn + 2 * j2 + 1) * FEAT_PITCH + tm + i] = s1;
        }
    }
    __syncthreads();

    // ======================= GEMM2: [64,160] @ [160,64] =====================
    const int tn2 = (tid >> 4) * 4;    // 4 cols = 2 packed pairs
    ull acc2p[4][2];
#pragma unroll
    for (int i = 0; i < 4; ++i) { acc2p[i][0] = 0ULL; acc2p[i][1] = 0ULL; }

#pragma unroll 4
    for (int k = 0; k < 160; ++k) {
        const float4 a4 = *reinterpret_cast<const float4*>(
            &s[OFF_HT + k * FEAT_PITCH + tm]);
        const ulonglong2 b2v = *reinterpret_cast<const ulonglong2*>(
            &W2[(size_t)k * 64 + tn2]);
        ull avd[4];
        avd[0] = pk2(a4.x, a4.x);
        avd[1] = pk2(a4.y, a4.y);
        avd[2] = pk2(a4.z, a4.z);
        avd[3] = pk2(a4.w, a4.w);
#pragma unroll
        for (int i = 0; i < 4; ++i) {
            fma2(acc2p[i][0], avd[i], b2v.x);
            fma2(acc2p[i][1], avd[i], b2v.y);
        }
    }
    __syncthreads();   // all reads of hT done; alpha overlays it

    // alphas -> smem ; batch -> smem
    {
        const float b_0 = b2[tn2 + 0], b_1 = b2[tn2 + 1];
        const float b_2 = b2[tn2 + 2], b_3 = b2[tn2 + 3];
#pragma unroll
        for (int i = 0; i < 4; ++i) {
            float a0, a1, a2, a3;
            upk2(a0, a1, acc2p[i][0]);
            upk2(a2, a3, acc2p[i][1]);
            float* ap = &s[OFF_ALPHA + (tm + i) * 65 + tn2];
            ap[0] = a0 + b_0;
            ap[1] = a1 + b_1;
            ap[2] = a2 + b_2;
            ap[3] = a3 + b_3;
        }
    }
    if (tid < MTILE)
        reinterpret_cast<int*>(s)[OFF_BATCH + tid] =
            (tid < mlim) ? batch[m0 + tid] : -1;
    __syncthreads();

    // ================ epilogue: gated sum, symmetrize, rotate ===============
    const int node = tid >> 2;   // 0..63
    const int jj   = tid & 3;    // 16 channels each
    float g[9];
#pragma unroll
    for (int k = 0; k < 9; ++k) g[k] = 0.0f;

    if (node < mlim) {
        const float4* tp4 = reinterpret_cast<const float4*>(
            t + ((size_t)(m0 + node) * 64 + jj * 16) * 9);
        const float* ap = &s[OFF_ALPHA + node * 65 + jj * 16];
#pragma unroll
        for (int cb = 0; cb < 4; ++cb) {
            float4 q[9];
#pragma unroll
            for (int u = 0; u < 9; ++u) q[u] = tp4[cb * 9 + u];
            const float* f = reinterpret_cast<const float*>(q);
            float al[4];
#pragma unroll
            for (int c = 0; c < 4; ++c) al[c] = ap[cb * 4 + c];
#pragma unroll
            for (int c = 0; c < 4; ++c)
#pragma unroll
                for (int k = 0; k < 9; ++k)
                    g[k] = fmaf(al[c], f[c * 9 + k], g[k]);
        }
    }

    // reduce across the 4 lanes of this node
#pragma unroll
    for (int k = 0; k < 9; ++k) {
        g[k] += __shfl_xor_sync(0xFFFFFFFFu, g[k], 1);
        g[k] += __shfl_xor_sync(0xFFFFFFFFu, g[k], 2);
    }

    if (jj == 0) {
        float G[9];
        if (node < mlim) {
            float S[9];
#pragma unroll
            for (int a = 0; a < 3; ++a)
#pragma unroll
                for (int b = 0; b < 3; ++b)
                    S[a * 3 + b] = 0.5f * (g[a * 3 + b] + g[b * 3 + a]);
            const float* rp = frames + (size_t)(m0 + node) * 9;
            float R[9];
#pragma unroll
            for (int k = 0; k < 9; ++k) R[k] = rp[k];
            float P[9];
#pragma unroll
            for (int a = 0; a < 3; ++a)
#pragma unroll
                for (int c = 0; c < 3; ++c)
                    P[a * 3 + c] = R[a * 3 + 0] * S[0 * 3 + c]
                                 + R[a * 3 + 1] * S[1 * 3 + c]
                                 + R[a * 3 + 2] * S[2 * 3 + c];
#pragma unroll
            for (int a = 0; a < 3; ++a)
#pragma unroll
                for (int d = 0; d < 3; ++d)
                    G[a * 3 + d] = P[a * 3 + 0] * R[d * 3 + 0]
                                 + P[a * 3 + 1] * R[d * 3 + 1]
                                 + P[a * 3 + 2] * R[d * 3 + 2];
        } else {
#pragma unroll
            for (int k = 0; k < 9; ++k) G[k] = 0.0f;
        }
#pragma unroll
        for (int k = 0; k < 9; ++k) s[OFF_GS + node * 9 + k] = G[k];
    }
    __syncthreads();

    // ============ sorted-run segment sum: few atomics per block =============
    if (tid < 9) {
        const int* bs = reinterpret_cast<const int*>(s) + OFF_BATCH;
        int cur = bs[0];
        float run = 0.0f;
        for (int n = 0; n < mlim; ++n) {
            int b = bs[n];
            if (b != cur) {
                if ((unsigned)cur < (unsigned)num_graphs)
                    atomicAdd(&out[(size_t)cur * 9 + tid], run);
                run = 0.0f;
                cur = b;
            }
            run += s[OFF_GS + n * 9 + tid];
        }
        if ((unsigned)cur < (unsigned)num_graphs)
            atomicAdd(&out[(size_t)cur * 9 + tid], run);
    }
}

extern "C" void kernel_launch(void* const* d_in, const int* in_sizes, int n_in,
                              void* d_out, int out_size)
{
    const float* h      = (const float*)d_in[0];
    const float* v      = (const float*)d_in[1];
    const float* t      = (const float*)d_in[2];
    const float* frames = (const float*)d_in[3];
    const int*   batch  = (const int*)d_in[4];
    const float* W1     = (const float*)d_in[5];
    const float* b1     = (const float*)d_in[6];
    const float* W2     = (const float*)d_in[7];
    const float* b2     = (const float*)d_in[8];
    float* out = (float*)d_out;

    const int N = in_sizes[0] / 128;
    const int num_graphs = out_size / 9;

    cudaMemsetAsync(d_out, 0, (size_t)out_size * sizeof(float));

    cudaFuncSetAttribute(tensor_message_fused,
                         cudaFuncAttributeMaxDynamicSharedMemorySize, SMEM_BYTES);

    const int grid = (N + MTILE - 1) / MTILE;
    tensor_message_fused<<<grid, NTHREADS, SMEM_BYTES>>>(
        h, v, t, frames, batch, W1, b1, W2, b2, out, N, num_graphs);
}

// round 6
// speedup vs baseline: 1.3704x; 1.0410x over previous
#include <cuda_runtime.h>
#include <math.h>

// ---------------------------------------------------------------------------
// Round 6: cut L1 wavefronts in the two t-reading phases via coalesced smem
// staging with bank-engineered layouts. GEMM structure = round 3 (best).
//   - t stage pitch 164 floats/node: epilogue LDS addr = 164n + 9jj + c is
//     conflict-free (4n+9jj distinct mod 32 for n<8, jj<4).
//   - v stage pitch 96: warp = one node, stride-3 reads conflict-free.
//   - launch_bounds(256,3): no register-cap rematerialization tax.
// ---------------------------------------------------------------------------

#define MTILE 64
#define NTHREADS 256
#define FEAT_PITCH 68
#define TPITCH 164                // t-stage floats per node (41 float4)
#define TPITCH4 41

// smem float offsets
#define OFF_FEAT   0              // feat chunk [32][68]  -> 2176
#define OFF_W1S    2176           // W1 chunk [32][160]   -> 5120 (end 7296)
#define OFF_STAGE  7296           // slab stage 64*164    -> 10496 (end 17792)
#define OFF_HT     0              // hT [160][68] = 10880 (phase 2)
#define OFF_ALPHA  0              // alpha [64][65] = 4160 (phase 3+)
#define OFF_GS     4352           // Gs [64][9] = 576
#define OFF_BATCH  4928           // batch[64] ints
#define SMEM_FLOATS 17792
#define SMEM_BYTES  (SMEM_FLOATS * 4)

typedef unsigned long long ull;

__device__ __forceinline__ ull pk2(float x, float y) {
    ull r; asm("mov.b64 %0, {%1, %2};" : "=l"(r) : "f"(x), "f"(y)); return r;
}
__device__ __forceinline__ void upk2(float& x, float& y, ull v) {
    asm("mov.b64 {%0, %1}, %2;" : "=f"(x), "=f"(y) : "l"(v));
}
__device__ __forceinline__ void fma2(ull& d, ull a, ull b) {
    asm("fma.rn.f32x2 %0, %1, %2, %0;" : "+l"(d) : "l"(a), "l"(b));
}

__global__ void __launch_bounds__(NTHREADS, 3)
tensor_message_fused(const float* __restrict__ h,
                     const float* __restrict__ v,
                     const float* __restrict__ t,
                     const float* __restrict__ frames,
                     const int* __restrict__ batch,
                     const float* __restrict__ W1,
                     const float* __restrict__ b1,
                     const float* __restrict__ W2,
                     const float* __restrict__ b2,
                     float* __restrict__ out,
                     int N, int num_graphs)
{
    extern __shared__ float s[];
    float4* stage4 = reinterpret_cast<float4*>(&s[OFF_STAGE]);
    const int tid = threadIdx.x;
    const int m0  = blockIdx.x * MTILE;
    const int mlim = (N - m0 < MTILE) ? (N - m0) : MTILE;

    // ======================= GEMM1: [64,320] @ [320,160] ====================
    const int tm  = (tid & 15) * 4;    // 4 node-rows
    const int tn  = (tid >> 4) * 10;   // 10 hidden cols (5 packed pairs)

    ull accp[4][5];
#pragma unroll
    for (int i = 0; i < 4; ++i)
#pragma unroll
        for (int j = 0; j < 5; ++j) accp[i][j] = 0ULL;

    for (int kc = 0; kc < 320; kc += 32) {
        // ---- build feature chunk [32 k-rows][64 nodes] ----
        if (kc < 128) {
            // h channels: warp reads 128B line per instr (coalesced)
            for (int i = tid; i < MTILE * 32; i += NTHREADS) {
                int m = i >> 5, k = i & 31;
                float val = 0.0f;
                if (m < mlim) val = h[(size_t)(m0 + m) * 128 + kc + k];
                s[OFF_FEAT + k * FEAT_PITCH + m] = val;
            }
        } else if (kc < 192) {
            // ---- v slab (32 channels): coalesced f4 copy, norms from LDS ----
            const int j0 = kc - 128;                     // 0 or 32
            const float4 z4 = make_float4(0.f, 0.f, 0.f, 0.f);
            for (int i = tid; i < MTILE * 24; i += NTHREADS) {
                int node = i / 24, q = i - node * 24;
                stage4[node * 24 + q] = (node < mlim)
                    ? reinterpret_cast<const float4*>(v)[
                          (size_t)(m0 + node) * 48 + (j0 >> 2) * 3 + q]
                    : z4;
            }
            __syncthreads();
            for (int i = tid; i < MTILE * 32; i += NTHREADS) {
                int m = i >> 5, k = i & 31;              // warp = one node
                const float* sp = &s[OFF_STAGE + m * 96 + k * 3];
                float x = sp[0], y = sp[1], z = sp[2];
                s[OFF_FEAT + k * FEAT_PITCH + m] = sqrtf(x*x + y*y + z*z);
            }
        } else {
            // ---- t slab (16 channels): coalesced f4 copy, invariants LDS ----
            const int c0 = (kc - 192) >> 1;              // 0,16,32,48
            const float4 z4 = make_float4(0.f, 0.f, 0.f, 0.f);
            for (int i = tid; i < MTILE * 36; i += NTHREADS) {
                int node = i / 36, q = i - node * 36;
                stage4[node * TPITCH4 + q] = (node < mlim)
                    ? reinterpret_cast<const float4*>(t)[
                          (size_t)(m0 + node) * 144 + (c0 >> 2) * 9 + q]
                    : z4;
            }
            __syncthreads();
            for (int i = tid; i < MTILE * 16; i += NTHREADS) {
                int m = i >> 4, cc = i & 15;
                const float* sp = &s[OFF_STAGE + m * TPITCH + cc * 9];
                float q0 = sp[0], q1 = sp[1], q2 = sp[2];
                float q3 = sp[3], q4 = sp[4], q5 = sp[5];
                float q6 = sp[6], q7 = sp[7], q8 = sp[8];
                float tr = q0 + q4 + q8;
                float fb = sqrtf(q0*q0 + q1*q1 + q2*q2 + q3*q3 + q4*q4 +
                                 q5*q5 + q6*q6 + q7*q7 + q8*q8);
                s[OFF_FEAT + (2 * cc)     * FEAT_PITCH + m] = tr;
                s[OFF_FEAT + (2 * cc + 1) * FEAT_PITCH + m] = fb;
            }
        }
        // ---- stage W1 chunk [32][160] (linear copy) ----
        for (int i = tid; i < 32 * 160; i += NTHREADS)
            s[OFF_W1S + i] = W1[(size_t)kc * 160 + i];
        __syncthreads();

#pragma unroll 4
        for (int k = 0; k < 32; ++k) {
            const float4 a4 = *reinterpret_cast<const float4*>(
                &s[OFF_FEAT + k * FEAT_PITCH + tm]);
            ull avd[4];
            avd[0] = pk2(a4.x, a4.x);
            avd[1] = pk2(a4.y, a4.y);
            avd[2] = pk2(a4.z, a4.z);
            avd[3] = pk2(a4.w, a4.w);
            const ull* bp = reinterpret_cast<const ull*>(
                &s[OFF_W1S + k * 160 + tn]);
            ull bv2[5];
#pragma unroll
            for (int j = 0; j < 5; ++j) bv2[j] = bp[j];
#pragma unroll
            for (int i = 0; i < 4; ++i)
#pragma unroll
                for (int j = 0; j < 5; ++j)
                    fma2(accp[i][j], avd[i], bv2[j]);
        }
        __syncthreads();
    }

    // bias + SiLU -> hT
#pragma unroll
    for (int j2 = 0; j2 < 5; ++j2) {
        const float b_lo = b1[tn + 2 * j2];
        const float b_hi = b1[tn + 2 * j2 + 1];
#pragma unroll
        for (int i = 0; i < 4; ++i) {
            float lo, hi;
            upk2(lo, hi, accp[i][j2]);
            float x0 = lo + b_lo, x1 = hi + b_hi;
            float s0 = x0 / (1.0f + __expf(-x0));
            float s1 = x1 / (1.0f + __expf(-x1));
            s[OFF_HT + (tn + 2 * j2)     * FEAT_PITCH + tm + i] = s0;
            s[OFF_HT + (tn + 2 * j2 + 1) * FEAT_PITCH + tm + i] = s1;
        }
    }
    __syncthreads();

    // ======================= GEMM2: [64,160] @ [160,64] =====================
    const int tn2 = (tid >> 4) * 4;
    ull acc2p[4][2];
#pragma unroll
    for (int i = 0; i < 4; ++i) { acc2p[i][0] = 0ULL; acc2p[i][1] = 0ULL; }

#pragma unroll 4
    for (int k = 0; k < 160; ++k) {
        const float4 a4 = *reinterpret_cast<const float4*>(
            &s[OFF_HT + k * FEAT_PITCH + tm]);
        const ulonglong2 b2v = *reinterpret_cast<const ulonglong2*>(
            &W2[(size_t)k * 64 + tn2]);
        ull avd[4];
        avd[0] = pk2(a4.x, a4.x);
        avd[1] = pk2(a4.y, a4.y);
        avd[2] = pk2(a4.z, a4.z);
        avd[3] = pk2(a4.w, a4.w);
#pragma unroll
        for (int i = 0; i < 4; ++i) {
            fma2(acc2p[i][0], avd[i], b2v.x);
            fma2(acc2p[i][1], avd[i], b2v.y);
        }
    }
    __syncthreads();   // hT reads done; alpha overlays

    // alphas + batch -> smem
    {
        const float b_0 = b2[tn2 + 0], b_1 = b2[tn2 + 1];
        const float b_2 = b2[tn2 + 2], b_3 = b2[tn2 + 3];
#pragma unroll
        for (int i = 0; i < 4; ++i) {
            float a0, a1, a2, a3;
            upk2(a0, a1, acc2p[i][0]);
            upk2(a2, a3, acc2p[i][1]);
            float* ap = &s[OFF_ALPHA + (tm + i) * 65 + tn2];
            ap[0] = a0 + b_0;
            ap[1] = a1 + b_1;
            ap[2] = a2 + b_2;
            ap[3] = a3 + b_3;
        }
    }
    if (tid < MTILE)
        reinterpret_cast<int*>(s)[OFF_BATCH + tid] =
            (tid < mlim) ? batch[m0 + tid] : -1;
    __syncthreads();

    // ============== epilogue: staged gated sum over 4 t-chunks ==============
    const int node = tid >> 2;   // 0..63
    const int jj   = tid & 3;    // owns channels jj, jj+4, jj+8, jj+12 / chunk
    float g[9];
#pragma unroll
    for (int k = 0; k < 9; ++k) g[k] = 0.0f;

    const float4 z4 = make_float4(0.f, 0.f, 0.f, 0.f);
    for (int chunk = 0; chunk < 4; ++chunk) {
        // coalesced copy: 16 channels x 64 nodes
        for (int i = tid; i < MTILE * 36; i += NTHREADS) {
            int nd = i / 36, q = i - nd * 36;
            stage4[nd * TPITCH4 + q] = (nd < mlim)
                ? reinterpret_cast<const float4*>(t)[
                      (size_t)(m0 + nd) * 144 + chunk * 36 + q]
                : z4;
        }
        __syncthreads();
        if (node < mlim) {
            const float* ap = &s[OFF_ALPHA + node * 65 + chunk * 16];
#pragma unroll
            for (int cc = 0; cc < 4; ++cc) {
                const int ch = jj + 4 * cc;
                const float al = ap[ch];
                const float* f = &s[OFF_STAGE + node * TPITCH + ch * 9];
#pragma unroll
                for (int k = 0; k < 9; ++k)
                    g[k] = fmaf(al, f[k], g[k]);
            }
        }
        __syncthreads();   // protect stage before next chunk's copy
    }

    // reduce across the 4 lanes of this node
#pragma unroll
    for (int k = 0; k < 9; ++k) {
        g[k] += __shfl_xor_sync(0xFFFFFFFFu, g[k], 1);
        g[k] += __shfl_xor_sync(0xFFFFFFFFu, g[k], 2);
    }

    if (jj == 0) {
        float G[9];
        if (node < mlim) {
            float S[9];
#pragma unroll
            for (int a = 0; a < 3; ++a)
#pragma unroll
                for (int b = 0; b < 3; ++b)
                    S[a * 3 + b] = 0.5f * (g[a * 3 + b] + g[b * 3 + a]);
            const float* rp = frames + (size_t)(m0 + node) * 9;
            float R[9];
#pragma unroll
            for (int k = 0; k < 9; ++k) R[k] = rp[k];
            float P[9];
#pragma unroll
            for (int a = 0; a < 3; ++a)
#pragma unroll
                for (int c = 0; c < 3; ++c)
                    P[a * 3 + c] = R[a * 3 + 0] * S[0 * 3 + c]
                                 + R[a * 3 + 1] * S[1 * 3 + c]
                                 + R[a * 3 + 2] * S[2 * 3 + c];
#pragma unroll
            for (int a = 0; a < 3; ++a)
#pragma unroll
                for (int d = 0; d < 3; ++d)
                    G[a * 3 + d] = P[a * 3 + 0] * R[d * 3 + 0]
                                 + P[a * 3 + 1] * R[d * 3 + 1]
                                 + P[a * 3 + 2] * R[d * 3 + 2];
        } else {
#pragma unroll
            for (int k = 0; k < 9; ++k) G[k] = 0.0f;
        }
#pragma unroll
        for (int k = 0; k < 9; ++k) s[OFF_GS + node * 9 + k] = G[k];
    }
    __syncthreads();

    // ============ sorted-run segment sum: few atomics per block =============
    if (tid < 9) {
        const int* bs = reinterpret_cast<const int*>(s) + OFF_BATCH;
        int cur = bs[0];
        float run = 0.0f;
        for (int n = 0; n < mlim; ++n) {
            int b = bs[n];
            if (b != cur) {
                if ((unsigned)cur < (unsigned)num_graphs)
                    atomicAdd(&out[(size_t)cur * 9 + tid], run);
                run = 0.0f;
                cur = b;
            }
            run += s[OFF_GS + n * 9 + tid];
        }
        if ((unsigned)cur < (unsigned)num_graphs)
            atomicAdd(&out[(size_t)cur * 9 + tid], run);
    }
}

extern "C" void kernel_launch(void* const* d_in, const int* in_sizes, int n_in,
                              void* d_out, int out_size)
{
    const float* h      = (const float*)d_in[0];
    const float* v      = (const float*)d_in[1];
    const float* t      = (const float*)d_in[2];
    const float* frames = (const float*)d_in[3];
    const int*   batch  = (const int*)d_in[4];
    const float* W1     = (const float*)d_in[5];
    const float* b1     = (const float*)d_in[6];
    const float* W2     = (const float*)d_in[7];
    const float* b2     = (const float*)d_in[8];
    float* out = (float*)d_out;

    const int N = in_sizes[0] / 128;
    const int num_graphs = out_size / 9;

    cudaMemsetAsync(d_out, 0, (size_t)out_size * sizeof(float));

    cudaFuncSetAttribute(tensor_message_fused,
                         cudaFuncAttributeMaxDynamicSharedMemorySize, SMEM_BYTES);

    const int grid = (N + MTILE - 1) / MTILE;
    tensor_message_fused<<<grid, NTHREADS, SMEM_BYTES>>>(
        h, v, t, frames, batch, W1, b1, W2, b2, out, N, num_graphs);
}